// round 5
// baseline (speedup 1.0000x reference)
#include <cuda_runtime.h>

#define NN 100000
#define NE 3200000
#define TOT (NE + NN)
#define NLAYER 31

// ---------------- scratch (static device globals; no allocation) -------------
__device__ int   g_is64;
__device__ int   g_deg[NN];
__device__ int   g_cursor[NN];
__device__ float g_dinv[NN];
__device__ int   g_ptr[NN + 1];
__device__ int   g_bsum[512];
__device__ int   g_boff[512];
__device__ int2  g_edges[TOT];          // {src, __float_as_int(norm)}
__device__ float g_hA[NN * 32];
__device__ float g_hB[NN * 32];

// ---------------- edge-index dtype detection ---------------------------------
// If the buffer really holds int64 node ids, the first 256 int64 values are all
// in [0, NN). If it holds int32, an int64 view fuses two random ids -> huge.
__global__ void k_detect(const void* __restrict__ ei) {
    const long long* p = (const long long*)ei;
    int ok = 1;
    for (int i = 0; i < 256; i++) {
        long long v = p[i];
        if (v < 0 || v >= NN) { ok = 0; break; }
    }
    g_is64 = ok;
}

__device__ __forceinline__ int edge_at(const void* ei, long long idx, int is64) {
    if (is64) return (int)((const long long*)ei)[idx];
    return ((const int*)ei)[idx];
}

// ---------------- preprocessing ----------------------------------------------

__global__ void k_init_deg() {
    int i = blockIdx.x * blockDim.x + threadIdx.x;
    if (i < NN) g_deg[i] = 1;                 // self-loop
}

__global__ void k_count(const void* __restrict__ ei) {
    int is64 = g_is64;
    int e = blockIdx.x * blockDim.x + threadIdx.x;
    if (e < NE) {
        int c = edge_at(ei, (long long)NE + e, is64);   // col (destination)
        atomicAdd(&g_deg[c], 1);
    }
}

__global__ void k_dinv() {
    int i = blockIdx.x * blockDim.x + threadIdx.x;
    if (i < NN) g_dinv[i] = rsqrtf((float)g_deg[i]);
}

__device__ __forceinline__ int block_excl_scan(int v) {
    __shared__ int sh[32];
    int lane = threadIdx.x & 31, wid = threadIdx.x >> 5;
    int x = v;
#pragma unroll
    for (int o = 1; o < 32; o <<= 1) {
        int t = __shfl_up_sync(0xffffffffu, x, o);
        if (lane >= o) x += t;
    }
    if (lane == 31) sh[wid] = x;
    __syncthreads();
    if (wid == 0) {
        int nw = blockDim.x >> 5;
        int s = (lane < nw) ? sh[lane] : 0;
#pragma unroll
        for (int o = 1; o < 32; o <<= 1) {
            int t = __shfl_up_sync(0xffffffffu, s, o);
            if (lane >= o) s += t;
        }
        sh[lane] = s;                          // inclusive warp-sums scan
    }
    __syncthreads();
    int wofs = wid ? sh[wid - 1] : 0;
    return wofs + x - v;                       // exclusive scan of v
}

__global__ void k_scanA() {
    int i = blockIdx.x * 256 + threadIdx.x;
    int v = (i < NN) ? g_deg[i] : 0;
    __shared__ int sh[8];
    int lane = threadIdx.x & 31, wid = threadIdx.x >> 5;
#pragma unroll
    for (int o = 16; o; o >>= 1) v += __shfl_down_sync(0xffffffffu, v, o);
    if (lane == 0) sh[wid] = v;
    __syncthreads();
    if (threadIdx.x == 0) {
        int s = 0;
#pragma unroll
        for (int w = 0; w < 8; w++) s += sh[w];
        g_bsum[blockIdx.x] = s;
    }
}

__global__ void k_scanB(int nb) {
    int v = ((int)threadIdx.x < nb) ? g_bsum[threadIdx.x] : 0;
    int ex = block_excl_scan(v);
    if ((int)threadIdx.x < nb) g_boff[threadIdx.x] = ex;
    if (threadIdx.x == blockDim.x - 1) g_ptr[NN] = ex + v;   // = TOT
}

__global__ void k_scanC() {
    int b = blockIdx.x;
    int i = b * 256 + threadIdx.x;
    int v = (i < NN) ? g_deg[i] : 0;
    int ex = block_excl_scan(v) + g_boff[b];
    if (i < NN) { g_ptr[i] = ex; g_cursor[i] = ex; }
}

__global__ void k_fill(const void* __restrict__ ei) {
    int is64 = g_is64;
    int t = blockIdx.x * blockDim.x + threadIdx.x;
    if (t >= TOT) return;
    int s, d;
    if (t < NE) { s = edge_at(ei, t, is64); d = edge_at(ei, (long long)NE + t, is64); }
    else        { s = d = t - NE; }            // self-loop
    float w = g_dinv[s] * g_dinv[d];
    int pos = atomicAdd(&g_cursor[d], 1);
    g_edges[pos] = make_int2(s, __float_as_int(w));
}

// ---------------- conv0: h = x @ W0 + b0  (128 -> 32) ------------------------
// 4 nodes/warp, 8 lanes/node, lane holds 4 output channels.
__global__ void k_conv0(const float4* __restrict__ x4,
                        const float* __restrict__ W0,
                        const float* __restrict__ b0) {
    __shared__ float sW[128 * 32];
    __shared__ float sb[32];
    for (int i = threadIdx.x; i < 128 * 32; i += blockDim.x) sW[i] = W0[i];
    if (threadIdx.x < 32) sb[threadIdx.x] = b0[threadIdx.x];
    __syncthreads();

    int lane = threadIdx.x & 31, wid = threadIdx.x >> 5;
    int sl = lane & 7;
    int n = blockIdx.x * 32 + wid * 4 + (lane >> 3);
    bool valid = (n < NN);

    float4 xr[4];
#pragma unroll
    for (int ch = 0; ch < 4; ch++)
        xr[ch] = valid ? x4[n * 32 + ch * 8 + sl] : make_float4(0.f, 0.f, 0.f, 0.f);

    const float4* sW4 = (const float4*)sW;
    const float4* sb4 = (const float4*)sb;
    float4 o = sb4[sl];
#pragma unroll
    for (int k = 0; k < 128; k++) {
        float4 xc = xr[k >> 5];
        float src = ((k & 3) == 0) ? xc.x : ((k & 3) == 1) ? xc.y
                  : ((k & 3) == 2) ? xc.z : xc.w;
        float a = __shfl_sync(0xffffffffu, src, (lane & 24) | ((k >> 2) & 7));
        float4 w = sW4[k * 8 + sl];
        o.x += a * w.x; o.y += a * w.y; o.z += a * w.z; o.w += a * w.w;
    }
    if (valid) ((float4*)g_hA)[n * 8 + sl] = o;
}

// ---------------- fused SGConv layer -----------------------------------------
// agg = sum_e norm * h_in[src];  h_out = relu(agg @ W + b)
__global__ void k_layer(const float* __restrict__ W,
                        const float* __restrict__ b,
                        int dir) {                 // 0: A->B, 1: B->A
    __shared__ float sW[32 * 32];
    __shared__ float sb[32];
    for (int i = threadIdx.x; i < 1024; i += blockDim.x) sW[i] = W[i];
    if (threadIdx.x < 32) sb[threadIdx.x] = b[threadIdx.x];
    __syncthreads();

    const float4* hin = dir ? (const float4*)g_hB : (const float4*)g_hA;
    float4*       hout = dir ? (float4*)g_hA : (float4*)g_hB;

    int lane = threadIdx.x & 31, wid = threadIdx.x >> 5;
    int sl = lane & 7;
    int n = blockIdx.x * 32 + wid * 4 + (lane >> 3);
    int beg = 0, end = 0;
    if (n < NN) { beg = g_ptr[n]; end = g_ptr[n + 1]; }

    float4 a0 = make_float4(0.f, 0.f, 0.f, 0.f);
    float4 a1 = make_float4(0.f, 0.f, 0.f, 0.f);
    int j = beg;
    for (; j + 1 < end; j += 2) {
        int2 e0 = __ldg(&g_edges[j]);
        int2 e1 = __ldg(&g_edges[j + 1]);
        float w0 = __int_as_float(e0.y);
        float w1 = __int_as_float(e1.y);
        float4 h0 = __ldg(&hin[e0.x * 8 + sl]);
        float4 h1 = __ldg(&hin[e1.x * 8 + sl]);
        a0.x += w0 * h0.x; a0.y += w0 * h0.y; a0.z += w0 * h0.z; a0.w += w0 * h0.w;
        a1.x += w1 * h1.x; a1.y += w1 * h1.y; a1.z += w1 * h1.z; a1.w += w1 * h1.w;
    }
    if (j < end) {
        int2 e = __ldg(&g_edges[j]);
        float w = __int_as_float(e.y);
        float4 h = __ldg(&hin[e.x * 8 + sl]);
        a0.x += w * h.x; a0.y += w * h.y; a0.z += w * h.z; a0.w += w * h.w;
    }
    float4 acc = make_float4(a0.x + a1.x, a0.y + a1.y, a0.z + a1.z, a0.w + a1.w);

    // 32x32 GEMM epilogue: o[cp] = b[cp] + sum_c acc[c] * W[c][cp]
    const float4* sW4 = (const float4*)sW;
    const float4* sb4 = (const float4*)sb;
    float4 o = sb4[sl];
#pragma unroll
    for (int c = 0; c < 32; c++) {
        float src = ((c & 3) == 0) ? acc.x : ((c & 3) == 1) ? acc.y
                  : ((c & 3) == 2) ? acc.z : acc.w;
        float a = __shfl_sync(0xffffffffu, src, (lane & 24) | (c >> 2));
        float4 w = sW4[c * 8 + sl];
        o.x += a * w.x; o.y += a * w.y; o.z += a * w.z; o.w += a * w.w;
    }
    o.x = fmaxf(o.x, 0.f); o.y = fmaxf(o.y, 0.f);
    o.z = fmaxf(o.z, 0.f); o.w = fmaxf(o.w, 0.f);
    if (n < NN) hout[n * 8 + sl] = o;
}

// ---------------- conv32: out = h @ W32 + b32  (32 -> 64) --------------------
__global__ void k_conv32(const float* __restrict__ W,
                         const float* __restrict__ b,
                         float4* __restrict__ out4) {
    __shared__ float sW[32 * 64];
    __shared__ float sb[64];
    for (int i = threadIdx.x; i < 32 * 64; i += blockDim.x) sW[i] = W[i];
    if (threadIdx.x < 64) sb[threadIdx.x] = b[threadIdx.x];
    __syncthreads();

    int lane = threadIdx.x & 31, wid = threadIdx.x >> 5;
    int sl = lane & 7;
    int n = blockIdx.x * 32 + wid * 4 + (lane >> 3);
    bool valid = (n < NN);

    const float4* hin = (const float4*)g_hB;   // last layer (l=30, even) wrote B
    float4 hv = valid ? hin[n * 8 + sl] : make_float4(0.f, 0.f, 0.f, 0.f);

    const float4* sW4 = (const float4*)sW;     // sW4[k*16 + c4] = W[k][c4*4..]
    const float4* sb4 = (const float4*)sb;
    float4 o0 = sb4[sl];
    float4 o1 = sb4[8 + sl];
#pragma unroll
    for (int k = 0; k < 32; k++) {
        float src = ((k & 3) == 0) ? hv.x : ((k & 3) == 1) ? hv.y
                  : ((k & 3) == 2) ? hv.z : hv.w;
        float a = __shfl_sync(0xffffffffu, src, (lane & 24) | (k >> 2));
        float4 w0 = sW4[k * 16 + sl];
        float4 w1 = sW4[k * 16 + 8 + sl];
        o0.x += a * w0.x; o0.y += a * w0.y; o0.z += a * w0.z; o0.w += a * w0.w;
        o1.x += a * w1.x; o1.y += a * w1.y; o1.z += a * w1.z; o1.w += a * w1.w;
    }
    if (valid) {
        out4[n * 16 + sl]     = o0;
        out4[n * 16 + 8 + sl] = o1;
    }
}

// ---------------- launcher ----------------------------------------------------

extern "C" void kernel_launch(void* const* d_in, const int* in_sizes, int n_in,
                              void* d_out, int out_size) {
    // Map inputs by element count (all distinct) — robust to ordering.
    const float* x = 0; const float* W0 = 0; const float* b0 = 0;
    const float* Ws = 0; const float* bs = 0; const float* W32 = 0;
    const float* b32 = 0; const void* ei = 0;
    for (int i = 0; i < n_in; i++) {
        long long sz = in_sizes[i];
        switch (sz) {
            case (long long)NN * 128: x   = (const float*)d_in[i]; break;
            case 128 * 32:            W0  = (const float*)d_in[i]; break;
            case 32:                  b0  = (const float*)d_in[i]; break;
            case NLAYER * 32 * 32:    Ws  = (const float*)d_in[i]; break;
            case NLAYER * 32:         bs  = (const float*)d_in[i]; break;
            case 32 * 64:             W32 = (const float*)d_in[i]; break;
            case 64:                  b32 = (const float*)d_in[i]; break;
            case 2LL * NE:            ei  = d_in[i];               break;
            default: break;
        }
    }

    const int nb_n = (NN + 255) / 256;                 // 391
    const int nb_e = (NE + 255) / 256;
    const int nb_t = (TOT + 255) / 256;
    const int nb_node = (NN + 31) / 32;                // 32 nodes / 256-thr block

    k_detect<<<1, 1>>>(ei);
    k_init_deg<<<nb_n, 256>>>();
    k_count<<<nb_e, 256>>>(ei);
    k_dinv<<<nb_n, 256>>>();
    k_scanA<<<nb_n, 256>>>();
    k_scanB<<<1, 512>>>(nb_n);
    k_scanC<<<nb_n, 256>>>();
    k_fill<<<nb_t, 256>>>(ei);

    k_conv0<<<nb_node, 256>>>((const float4*)x, W0, b0);

    for (int l = 0; l < NLAYER; l++)
        k_layer<<<nb_node, 256>>>(Ws + l * 32 * 32, bs + l * 32, l & 1);

    k_conv32<<<nb_node, 256>>>(W32, b32, (float4*)d_out);
}

// round 6
// speedup vs baseline: 1.6869x; 1.6869x over previous
#include <cuda_runtime.h>

#define NN 100000
#define NE 3200000
#define CAP (NE + 4 * NN)          // padded edge capacity (pad <= +3 per node)
#define NLAYER 31

// ---------------- scratch (static device globals; no allocation) -------------
__device__ int   g_is64;
__device__ int   g_deg[NN];
__device__ int   g_cursor[NN];
__device__ float g_dinv[NN];
__device__ int   g_ptr[NN + 1];
__device__ int   g_bsum[512];
__device__ int   g_boff[512];
__device__ int   g_srcs[CAP];                  // src only; pad slots = NN (zero row)
__device__ float g_hA[(NN + 1) * 32];          // row NN is a zero row
__device__ float g_hB[(NN + 1) * 32];

// ---------------- edge-index dtype detection (parallel) ----------------------
__global__ void k_detect(const void* __restrict__ ei) {
    __shared__ int bad;
    if (threadIdx.x == 0) bad = 0;
    __syncthreads();
    long long v = ((const long long*)ei)[threadIdx.x];
    if (v < 0 || v >= NN) bad = 1;
    __syncthreads();
    if (threadIdx.x == 0) g_is64 = !bad;
}

__device__ __forceinline__ int edge_at(const void* ei, long long idx, int is64) {
    if (is64) return (int)((const long long*)ei)[idx];
    return ((const int*)ei)[idx];
}

// ---------------- preprocessing ----------------------------------------------

__global__ void k_init() {                     // deg=1 (self-loop) + src prefill
    int i = blockIdx.x * blockDim.x + threadIdx.x;
    if (i < NN) g_deg[i] = 1;
    if (i < CAP) g_srcs[i] = NN;               // points at zero row
}

__global__ void k_count(const void* __restrict__ ei) {
    int is64 = g_is64;
    int e = blockIdx.x * blockDim.x + threadIdx.x;
    if (e < NE) {
        int c = edge_at(ei, (long long)NE + e, is64);
        atomicAdd(&g_deg[c], 1);
    }
}

__device__ __forceinline__ int pad4(int d) { return (d + 3) & ~3; }

__device__ __forceinline__ int block_excl_scan(int v) {
    __shared__ int sh[32];
    int lane = threadIdx.x & 31, wid = threadIdx.x >> 5;
    int x = v;
#pragma unroll
    for (int o = 1; o < 32; o <<= 1) {
        int t = __shfl_up_sync(0xffffffffu, x, o);
        if (lane >= o) x += t;
    }
    if (lane == 31) sh[wid] = x;
    __syncthreads();
    if (wid == 0) {
        int nw = blockDim.x >> 5;
        int s = (lane < nw) ? sh[lane] : 0;
#pragma unroll
        for (int o = 1; o < 32; o <<= 1) {
            int t = __shfl_up_sync(0xffffffffu, s, o);
            if (lane >= o) s += t;
        }
        sh[lane] = s;
    }
    __syncthreads();
    int wofs = wid ? sh[wid - 1] : 0;
    return wofs + x - v;
}

__global__ void k_scanA() {                    // dinv + per-block sums of padded deg
    int i = blockIdx.x * 256 + threadIdx.x;
    int d = (i < NN) ? g_deg[i] : 0;
    if (i < NN) g_dinv[i] = rsqrtf((float)d);
    int v = pad4(d);
    __shared__ int sh[8];
    int lane = threadIdx.x & 31, wid = threadIdx.x >> 5;
#pragma unroll
    for (int o = 16; o; o >>= 1) v += __shfl_down_sync(0xffffffffu, v, o);
    if (lane == 0) sh[wid] = v;
    __syncthreads();
    if (threadIdx.x == 0) {
        int s = 0;
#pragma unroll
        for (int w = 0; w < 8; w++) s += sh[w];
        g_bsum[blockIdx.x] = s;
    }
}

__global__ void k_scanB(int nb) {
    int v = ((int)threadIdx.x < nb) ? g_bsum[threadIdx.x] : 0;
    int ex = block_excl_scan(v);
    if ((int)threadIdx.x < nb) g_boff[threadIdx.x] = ex;
    if (threadIdx.x == blockDim.x - 1) g_ptr[NN] = ex + v;
}

__global__ void k_scanC() {
    int b = blockIdx.x;
    int i = b * 256 + threadIdx.x;
    int v = (i < NN) ? pad4(g_deg[i]) : 0;
    int ex = block_excl_scan(v) + g_boff[b];
    if (i < NN) { g_ptr[i] = ex; g_cursor[i] = ex; }
}

__global__ void k_fill(const void* __restrict__ ei) {
    int is64 = g_is64;
    int t = blockIdx.x * blockDim.x + threadIdx.x;
    if (t >= NE + NN) return;
    int s, d;
    if (t < NE) { s = edge_at(ei, t, is64); d = edge_at(ei, (long long)NE + t, is64); }
    else        { s = d = t - NE; }            // self-loop
    int pos = atomicAdd(&g_cursor[d], 1);
    g_srcs[pos] = s;
}

// ---------------- conv0: p = dinv * (x @ W0 + b0)  (128 -> 32) ---------------
__global__ void k_conv0(const float4* __restrict__ x4,
                        const float* __restrict__ W0,
                        const float* __restrict__ b0) {
    __shared__ float sW[128 * 32];
    __shared__ float sb[32];
    for (int i = threadIdx.x; i < 128 * 32; i += blockDim.x) sW[i] = W0[i];
    if (threadIdx.x < 32) sb[threadIdx.x] = b0[threadIdx.x];
    // zero row NN of both h buffers (once; layers never write row NN)
    if (blockIdx.x == 0 && threadIdx.x < 32) {
        g_hA[NN * 32 + threadIdx.x] = 0.f;
        g_hB[NN * 32 + threadIdx.x] = 0.f;
    }
    __syncthreads();

    int lane = threadIdx.x & 31, wid = threadIdx.x >> 5;
    int sl = lane & 7;
    int n = blockIdx.x * 32 + wid * 4 + (lane >> 3);
    bool valid = (n < NN);

    float4 xr[4];
#pragma unroll
    for (int ch = 0; ch < 4; ch++)
        xr[ch] = valid ? x4[n * 32 + ch * 8 + sl] : make_float4(0.f, 0.f, 0.f, 0.f);

    const float4* sW4 = (const float4*)sW;
    const float4* sb4 = (const float4*)sb;
    float4 o = sb4[sl];
#pragma unroll
    for (int k = 0; k < 128; k++) {
        float4 xc = xr[k >> 5];
        float src = ((k & 3) == 0) ? xc.x : ((k & 3) == 1) ? xc.y
                  : ((k & 3) == 2) ? xc.z : xc.w;
        float a = __shfl_sync(0xffffffffu, src, (lane & 24) | ((k >> 2) & 7));
        float4 w = sW4[k * 8 + sl];
        o.x += a * w.x; o.y += a * w.y; o.z += a * w.z; o.w += a * w.w;
    }
    if (valid) {
        float dv = g_dinv[n];
        o.x *= dv; o.y *= dv; o.z *= dv; o.w *= dv;
        ((float4*)g_hA)[n * 8 + sl] = o;
    }
}

// ---------------- fused SGConv layer -----------------------------------------
// S = sum_{e in seg(n)} p_in[src];  agg = dinv[n]*S;  o = relu(agg @ W + b)
// store: p_out = (store_scaled ? dinv[n] : 1) * o
__global__ void __launch_bounds__(256)
k_layer(const float* __restrict__ W, const float* __restrict__ b,
        int dir, int store_scaled) {
    __shared__ float sW[32 * 32];
    __shared__ float sb[32];
    for (int i = threadIdx.x; i < 1024; i += blockDim.x) sW[i] = W[i];
    if (threadIdx.x < 32) sb[threadIdx.x] = b[threadIdx.x];
    __syncthreads();

    const float4* hin = dir ? (const float4*)g_hB : (const float4*)g_hA;
    float4*       hout = dir ? (float4*)g_hA : (float4*)g_hB;

    int lane = threadIdx.x & 31, wid = threadIdx.x >> 5;
    int sl = lane & 7;
    int n = blockIdx.x * 32 + wid * 4 + (lane >> 3);
    int beg = 0, end = 0;
    float dv = 0.f;
    if (n < NN) { beg = g_ptr[n]; end = g_ptr[n + 1]; dv = g_dinv[n]; }

    const int4* s4p = (const int4*)g_srcs;     // segments are 4-aligned
    float4 a0 = make_float4(0.f, 0.f, 0.f, 0.f);
    float4 a1 = make_float4(0.f, 0.f, 0.f, 0.f);
#pragma unroll 2
    for (int j = beg; j < end; j += 4) {
        int4 s4 = __ldg(&s4p[j >> 2]);
        float4 h0 = __ldg(&hin[s4.x * 8 + sl]);
        float4 h1 = __ldg(&hin[s4.y * 8 + sl]);
        float4 h2 = __ldg(&hin[s4.z * 8 + sl]);
        float4 h3 = __ldg(&hin[s4.w * 8 + sl]);
        a0.x += h0.x + h2.x; a0.y += h0.y + h2.y;
        a0.z += h0.z + h2.z; a0.w += h0.w + h2.w;
        a1.x += h1.x + h3.x; a1.y += h1.y + h3.y;
        a1.z += h1.z + h3.z; a1.w += h1.w + h3.w;
    }
    float4 acc;
    acc.x = (a0.x + a1.x) * dv; acc.y = (a0.y + a1.y) * dv;
    acc.z = (a0.z + a1.z) * dv; acc.w = (a0.w + a1.w) * dv;

    // 32x32 GEMM epilogue
    const float4* sW4 = (const float4*)sW;
    const float4* sb4 = (const float4*)sb;
    float4 o = sb4[sl];
#pragma unroll
    for (int c = 0; c < 32; c++) {
        float src = ((c & 3) == 0) ? acc.x : ((c & 3) == 1) ? acc.y
                  : ((c & 3) == 2) ? acc.z : acc.w;
        float a = __shfl_sync(0xffffffffu, src, (lane & 24) | (c >> 2));
        float4 w = sW4[c * 8 + sl];
        o.x += a * w.x; o.y += a * w.y; o.z += a * w.z; o.w += a * w.w;
    }
    float sc = store_scaled ? dv : 1.f;
    o.x = fmaxf(o.x, 0.f) * sc; o.y = fmaxf(o.y, 0.f) * sc;
    o.z = fmaxf(o.z, 0.f) * sc; o.w = fmaxf(o.w, 0.f) * sc;
    if (n < NN) hout[n * 8 + sl] = o;
}

// ---------------- conv32: out = h @ W32 + b32  (32 -> 64) --------------------
__global__ void k_conv32(const float* __restrict__ W,
                         const float* __restrict__ b,
                         float4* __restrict__ out4) {
    __shared__ float sW[32 * 64];
    __shared__ float sb[64];
    for (int i = threadIdx.x; i < 32 * 64; i += blockDim.x) sW[i] = W[i];
    if (threadIdx.x < 64) sb[threadIdx.x] = b[threadIdx.x];
    __syncthreads();

    int lane = threadIdx.x & 31, wid = threadIdx.x >> 5;
    int sl = lane & 7;
    int n = blockIdx.x * 32 + wid * 4 + (lane >> 3);
    bool valid = (n < NN);

    const float4* hin = (const float4*)g_hB;   // layer 30 (dir=0) wrote B, unscaled
    float4 hv = valid ? hin[n * 8 + sl] : make_float4(0.f, 0.f, 0.f, 0.f);

    const float4* sW4 = (const float4*)sW;
    const float4* sb4 = (const float4*)sb;
    float4 o0 = sb4[sl];
    float4 o1 = sb4[8 + sl];
#pragma unroll
    for (int k = 0; k < 32; k++) {
        float src = ((k & 3) == 0) ? hv.x : ((k & 3) == 1) ? hv.y
                  : ((k & 3) == 2) ? hv.z : hv.w;
        float a = __shfl_sync(0xffffffffu, src, (lane & 24) | (k >> 2));
        float4 w0 = sW4[k * 16 + sl];
        float4 w1 = sW4[k * 16 + 8 + sl];
        o0.x += a * w0.x; o0.y += a * w0.y; o0.z += a * w0.z; o0.w += a * w0.w;
        o1.x += a * w1.x; o1.y += a * w1.y; o1.z += a * w1.z; o1.w += a * w1.w;
    }
    if (valid) {
        out4[n * 16 + sl]     = o0;
        out4[n * 16 + 8 + sl] = o1;
    }
}

// ---------------- launcher ----------------------------------------------------

extern "C" void kernel_launch(void* const* d_in, const int* in_sizes, int n_in,
                              void* d_out, int out_size) {
    const float* x = 0; const float* W0 = 0; const float* b0 = 0;
    const float* Ws = 0; const float* bs = 0; const float* W32 = 0;
    const float* b32 = 0; const void* ei = 0;
    for (int i = 0; i < n_in; i++) {
        long long sz = in_sizes[i];
        switch (sz) {
            case (long long)NN * 128: x   = (const float*)d_in[i]; break;
            case 128 * 32:            W0  = (const float*)d_in[i]; break;
            case 32:                  b0  = (const float*)d_in[i]; break;
            case NLAYER * 32 * 32:    Ws  = (const float*)d_in[i]; break;
            case NLAYER * 32:         bs  = (const float*)d_in[i]; break;
            case 32 * 64:             W32 = (const float*)d_in[i]; break;
            case 64:                  b32 = (const float*)d_in[i]; break;
            case 2LL * NE:            ei  = d_in[i];               break;
            default: break;
        }
    }

    const int nb_n    = (NN + 255) / 256;              // 391
    const int nb_e    = (NE + 255) / 256;
    const int nb_t    = (NE + NN + 255) / 256;
    const int nb_cap  = (CAP + 255) / 256;
    const int nb_node = (NN + 31) / 32;                // 3125

    k_detect<<<1, 256>>>(ei);
    k_init<<<nb_cap, 256>>>();
    k_count<<<nb_e, 256>>>(ei);
    k_scanA<<<nb_n, 256>>>();
    k_scanB<<<1, 512>>>(nb_n);
    k_scanC<<<nb_n, 256>>>();
    k_fill<<<nb_t, 256>>>(ei);

    k_conv0<<<nb_node, 256>>>((const float4*)x, W0, b0);

    for (int l = 0; l < NLAYER; l++)
        k_layer<<<nb_node, 256>>>(Ws + l * 32 * 32, bs + l * 32,
                                  l & 1, l != NLAYER - 1);

    k_conv32<<<nb_node, 256>>>(W32, b32, (float4*)d_out);
}

// round 8
// speedup vs baseline: 1.7073x; 1.0121x over previous
#include <cuda_runtime.h>

#define NN 100000
#define NE 3200000
#define CAP (NE + 4 * NN)          // padded edge capacity (pad <= +3 per node)
#define NLAYER 31

// ---------------- scratch (static device globals; no allocation) -------------
__device__ int   g_is64;
__device__ int   g_total;
__device__ int   g_deg[NN];
__device__ int   g_cursor[NN];
__device__ float g_dinv[NN];
__device__ int2  g_seg[NN];                    // {beg, beg+pad4(deg)}
__device__ int   g_srcs[CAP];                  // src only; pad slots = NN (zero row)
__device__ float g_hA[(NN + 1) * 32];          // row NN is a zero row
__device__ float g_hB[(NN + 1) * 32];

__device__ __forceinline__ int edge_at(const void* ei, long long idx, int is64) {
    if (is64) return (int)((const long long*)ei)[idx];
    return ((const int*)ei)[idx];
}

__device__ __forceinline__ int pad4(int d) { return (d + 3) & ~3; }

// ---------------- init: deg=1, zero total, dtype detect ----------------------
__global__ void k_init(const void* __restrict__ ei) {
    int i = blockIdx.x * blockDim.x + threadIdx.x;
    if (i < NN) g_deg[i] = 1;                  // self-loop
    if (i == 0) g_total = 0;
    if (blockIdx.x == 0) {                     // parallel dtype detection
        __shared__ int bad;
        if (threadIdx.x == 0) bad = 0;
        __syncthreads();
        long long v = ((const long long*)ei)[threadIdx.x];
        if (v < 0 || v >= NN) bad = 1;
        __syncthreads();
        if (threadIdx.x == 0) g_is64 = !bad;
    }
}

__global__ void k_count(const void* __restrict__ ei) {
    int is64 = g_is64;
    int e = blockIdx.x * blockDim.x + threadIdx.x;
    if (e < NE) {
        int c = edge_at(ei, (long long)NE + e, is64);
        atomicAdd(&g_deg[c], 1);
    }
}

__device__ __forceinline__ int block_excl_scan(int v) {
    __shared__ int sh[32];
    int lane = threadIdx.x & 31, wid = threadIdx.x >> 5;
    int x = v;
#pragma unroll
    for (int o = 1; o < 32; o <<= 1) {
        int t = __shfl_up_sync(0xffffffffu, x, o);
        if (lane >= o) x += t;
    }
    if (lane == 31) sh[wid] = x;
    __syncthreads();
    if (wid == 0) {
        int nw = blockDim.x >> 5;
        int s = (lane < nw) ? sh[lane] : 0;
#pragma unroll
        for (int o = 1; o < 32; o <<= 1) {
            int t = __shfl_up_sync(0xffffffffu, s, o);
            if (lane >= o) s += t;
        }
        sh[lane] = s;
    }
    __syncthreads();
    int wofs = wid ? sh[wid - 1] : 0;
    return wofs + x - v;
}

// One-kernel "scan": order-free segment placement via per-block atomicAdd.
// Also computes dinv, writes cursor, and fills the <=3 pad slots per node.
__global__ void k_scan() {
    int i = blockIdx.x * 256 + threadIdx.x;
    int d = (i < NN) ? g_deg[i] : 0;
    if (i < NN) g_dinv[i] = rsqrtf((float)d);
    int p4 = (i < NN) ? pad4(d) : 0;
    int ex = block_excl_scan(p4);
    __shared__ int base;
    if (threadIdx.x == 255) base = atomicAdd(&g_total, ex + p4);
    __syncthreads();
    int off = base + ex;
    if (i < NN) {
        g_seg[i] = make_int2(off, off + p4);
        g_cursor[i] = off;
        for (int t = d; t < p4; t++) g_srcs[off + t] = NN;   // pad -> zero row
    }
}

__global__ void k_fill(const void* __restrict__ ei) {
    int is64 = g_is64;
    int t = blockIdx.x * blockDim.x + threadIdx.x;
    if (t >= NE + NN) return;
    int s, d;
    if (t < NE) { s = edge_at(ei, t, is64); d = edge_at(ei, (long long)NE + t, is64); }
    else        { s = d = t - NE; }            // self-loop
    int pos = atomicAdd(&g_cursor[d], 1);
    g_srcs[pos] = s;
}

// ---------------- conv0: p = dinv * (x @ W0 + b0)  (128 -> 32) ---------------
__global__ void k_conv0(const float4* __restrict__ x4,
                        const float* __restrict__ W0,
                        const float* __restrict__ b0) {
    __shared__ float sW[128 * 32];
    __shared__ float sb[32];
    for (int i = threadIdx.x; i < 128 * 32; i += blockDim.x) sW[i] = W0[i];
    if (threadIdx.x < 32) sb[threadIdx.x] = b0[threadIdx.x];
    // zero row NN of both h buffers (layers never write row NN)
    if (blockIdx.x == 0 && threadIdx.x < 32) {
        g_hA[NN * 32 + threadIdx.x] = 0.f;
        g_hB[NN * 32 + threadIdx.x] = 0.f;
    }
    __syncthreads();

    int lane = threadIdx.x & 31, wid = threadIdx.x >> 5;
    int sl = lane & 7;
    int n = blockIdx.x * 32 + wid * 4 + (lane >> 3);
    bool valid = (n < NN);

    float4 xr[4];
#pragma unroll
    for (int ch = 0; ch < 4; ch++)
        xr[ch] = valid ? x4[n * 32 + ch * 8 + sl] : make_float4(0.f, 0.f, 0.f, 0.f);

    const float4* sW4 = (const float4*)sW;
    const float4* sb4 = (const float4*)sb;
    float4 o = sb4[sl];
#pragma unroll
    for (int k = 0; k < 128; k++) {
        float4 xc = xr[k >> 5];
        float src = ((k & 3) == 0) ? xc.x : ((k & 3) == 1) ? xc.y
                  : ((k & 3) == 2) ? xc.z : xc.w;
        float a = __shfl_sync(0xffffffffu, src, (lane & 24) | ((k >> 2) & 7));
        float4 w = sW4[k * 8 + sl];
        o.x += a * w.x; o.y += a * w.y; o.z += a * w.z; o.w += a * w.w;
    }
    if (valid) {
        float dv = g_dinv[n];
        o.x *= dv; o.y *= dv; o.z *= dv; o.w *= dv;
        ((float4*)g_hA)[n * 8 + sl] = o;
    }
}

// ---------------- fused SGConv layer -----------------------------------------
// S = sum_{seg(n)} p_in[src];  agg = dinv[n]*S;  o = relu(agg @ W + b)
// store: p_out = (store_scaled ? dinv[n] : 1) * o
__global__ void __launch_bounds__(256)
k_layer(const float* __restrict__ W, const float* __restrict__ b,
        int dir, int store_scaled) {
    __shared__ float sW[32 * 32];
    __shared__ float sb[32];
    for (int i = threadIdx.x; i < 1024; i += blockDim.x) sW[i] = W[i];
    if (threadIdx.x < 32) sb[threadIdx.x] = b[threadIdx.x];
    __syncthreads();

    const float4* hin = dir ? (const float4*)g_hB : (const float4*)g_hA;
    float4*       hout = dir ? (float4*)g_hA : (float4*)g_hB;

    int lane = threadIdx.x & 31, wid = threadIdx.x >> 5;
    int sl = lane & 7;
    int n = blockIdx.x * 32 + wid * 4 + (lane >> 3);
    int beg = 0, end = 0;
    float dv = 0.f;
    if (n < NN) {
        int2 seg = __ldg(&g_seg[n]);
        beg = seg.x; end = seg.y;
        dv = g_dinv[n];
    }

    const int4* s4p = (const int4*)g_srcs;     // segments are 4-aligned
    float4 a0 = make_float4(0.f, 0.f, 0.f, 0.f);
    float4 a1 = make_float4(0.f, 0.f, 0.f, 0.f);
#pragma unroll 2
    for (int j = beg; j < end; j += 4) {
        int4 s4 = __ldg(&s4p[j >> 2]);
        float4 h0 = __ldg(&hin[s4.x * 8 + sl]);
        float4 h1 = __ldg(&hin[s4.y * 8 + sl]);
        float4 h2 = __ldg(&hin[s4.z * 8 + sl]);
        float4 h3 = __ldg(&hin[s4.w * 8 + sl]);
        a0.x += h0.x + h2.x; a0.y += h0.y + h2.y;
        a0.z += h0.z + h2.z; a0.w += h0.w + h2.w;
        a1.x += h1.x + h3.x; a1.y += h1.y + h3.y;
        a1.z += h1.z + h3.z; a1.w += h1.w + h3.w;
    }
    float4 acc;
    acc.x = (a0.x + a1.x) * dv; acc.y = (a0.y + a1.y) * dv;
    acc.z = (a0.z + a1.z) * dv; acc.w = (a0.w + a1.w) * dv;

    // 32x32 GEMM epilogue
    const float4* sW4 = (const float4*)sW;
    const float4* sb4 = (const float4*)sb;
    float4 o = sb4[sl];
#pragma unroll
    for (int c = 0; c < 32; c++) {
        float src = ((c & 3) == 0) ? acc.x : ((c & 3) == 1) ? acc.y
                  : ((c & 3) == 2) ? acc.z : acc.w;
        float a = __shfl_sync(0xffffffffu, src, (lane & 24) | (c >> 2));
        float4 w = sW4[c * 8 + sl];
        o.x += a * w.x; o.y += a * w.y; o.z += a * w.z; o.w += a * w.w;
    }
    float sc = store_scaled ? dv : 1.f;
    o.x = fmaxf(o.x, 0.f) * sc; o.y = fmaxf(o.y, 0.f) * sc;
    o.z = fmaxf(o.z, 0.f) * sc; o.w = fmaxf(o.w, 0.f) * sc;
    if (n < NN) hout[n * 8 + sl] = o;
}

// ---------------- conv32: out = h @ W32 + b32  (32 -> 64) --------------------
__global__ void k_conv32(const float* __restrict__ W,
                         const float* __restrict__ b,
                         float4* __restrict__ out4) {
    __shared__ float sW[32 * 64];
    __shared__ float sb[64];
    for (int i = threadIdx.x; i < 32 * 64; i += blockDim.x) sW[i] = W[i];
    if (threadIdx.x < 64) sb[threadIdx.x] = b[threadIdx.x];
    __syncthreads();

    int lane = threadIdx.x & 31, wid = threadIdx.x >> 5;
    int sl = lane & 7;
    int n = blockIdx.x * 32 + wid * 4 + (lane >> 3);
    bool valid = (n < NN);

    const float4* hin = (const float4*)g_hB;   // layer 30 (dir=0) wrote B, unscaled
    float4 hv = valid ? hin[n * 8 + sl] : make_float4(0.f, 0.f, 0.f, 0.f);

    const float4* sW4 = (const float4*)sW;
    const float4* sb4 = (const float4*)sb;
    float4 o0 = sb4[sl];
    float4 o1 = sb4[8 + sl];
#pragma unroll
    for (int k = 0; k < 32; k++) {
        float src = ((k & 3) == 0) ? hv.x : ((k & 3) == 1) ? hv.y
                  : ((k & 3) == 2) ? hv.z : hv.w;
        float a = __shfl_sync(0xffffffffu, src, (lane & 24) | (k >> 2));
        float4 w0 = sW4[k * 16 + sl];
        float4 w1 = sW4[k * 16 + 8 + sl];
        o0.x += a * w0.x; o0.y += a * w0.y; o0.z += a * w0.z; o0.w += a * w0.w;
        o1.x += a * w1.x; o1.y += a * w1.y; o1.z += a * w1.z; o1.w += a * w1.w;
    }
    if (valid) {
        out4[n * 16 + sl]     = o0;
        out4[n * 16 + 8 + sl] = o1;
    }
}

// ---------------- launcher ----------------------------------------------------

extern "C" void kernel_launch(void* const* d_in, const int* in_sizes, int n_in,
                              void* d_out, int out_size) {
    const float* x = 0; const float* W0 = 0; const float* b0 = 0;
    const float* Ws = 0; const float* bs = 0; const float* W32 = 0;
    const float* b32 = 0; const void* ei = 0;
    for (int i = 0; i < n_in; i++) {
        long long sz = in_sizes[i];
        switch (sz) {
            case (long long)NN * 128: x   = (const float*)d_in[i]; break;
            case 128 * 32:            W0  = (const float*)d_in[i]; break;
            case 32:                  b0  = (const float*)d_in[i]; break;
            case NLAYER * 32 * 32:    Ws  = (const float*)d_in[i]; break;
            case NLAYER * 32:         bs  = (const float*)d_in[i]; break;
            case 32 * 64:             W32 = (const float*)d_in[i]; break;
            case 64:                  b32 = (const float*)d_in[i]; break;
            case 2LL * NE:            ei  = d_in[i];               break;
            default: break;
        }
    }

    const int nb_n    = (NN + 255) / 256;              // 391
    const int nb_e    = (NE + 255) / 256;
    const int nb_t    = (NE + NN + 255) / 256;
    const int nb_node = (NN + 31) / 32;                // 3125

    k_init<<<nb_n, 256>>>(ei);                         // launch 0
    k_count<<<nb_e, 256>>>(ei);                        // 1
    k_scan<<<nb_n, 256>>>();                           // 2
    k_fill<<<nb_t, 256>>>(ei);                         // 3
    k_conv0<<<nb_node, 256>>>((const float4*)x, W0, b0);  // 4

    for (int l = 0; l < NLAYER; l++)                   // 5..35 (ncu hits layer0)
        k_layer<<<nb_node, 256>>>(Ws + l * 32 * 32, bs + l * 32,
                                  l & 1, l != NLAYER - 1);

    k_conv32<<<nb_node, 256>>>(W32, b32, (float4*)d_out);
}